// round 10
// baseline (speedup 1.0000x reference)
#include <cuda_runtime.h>
#include <cuda_bf16.h>
#include <math.h>

#define Ldim 4096
#define Edim 512
#define Sdim 1024
#define Hdim 150
#define HP   160
#define MAXN 10
#define Ttot 40915
#define TP   40960

// ---------------------------------------------------------------------------
// Device scratch (zero-init; pad regions never written -> stay zero)
// ---------------------------------------------------------------------------
__device__ float g_A[Ldim * HP];
__device__ float g_B[Ldim * HP];
__device__ float g_C[Ldim * HP];
__device__ float g_attn[Ldim];
__device__ float g_X[(size_t)TP * HP];   // pooled rows, fp32 (pad cols stay 0)
__device__ float g_sW3p[HP];
__device__ float g_sb2p[HP];
__device__ float g_aW3p[HP];
__device__ float g_ab2p[HP];

// bf16 hi/lo triplet buffers.  A-side slot pattern: [xh, xl, xh]
//                              B-side slot pattern: [bh, bh, bl]
__device__ __align__(16) __nv_bfloat16 g_Ss[(size_t)Ldim * 3072];
__device__ __align__(16) __nv_bfloat16 g_Es[(size_t)Ldim * 1536];
__device__ __align__(16) __nv_bfloat16 g_H1s[(size_t)Ldim * 480];
__device__ __align__(16) __nv_bfloat16 g_W1s[3 * 160 * 3072];
__device__ __align__(16) __nv_bfloat16 g_WCs[160 * 1536];
__device__ __align__(16) __nv_bfloat16 g_Wl2s[160 * 480];
__device__ __align__(16) __nv_bfloat16 g_W2s[160 * 480];

// ---------------------------------------------------------------------------
// Combined split kernel: activations + all weights + padded vectors
// ---------------------------------------------------------------------------
__global__ void split_all(const float* __restrict__ states,
                          const float* __restrict__ embeds,
                          const float* __restrict__ sW1,
                          const float* __restrict__ aW1,
                          const float* __restrict__ aW2,
                          const float* __restrict__ sW2,
                          const float* __restrict__ sW3,
                          const float* __restrict__ sb2,
                          const float* __restrict__ aW3,
                          const float* __restrict__ ab2)
{
    int idx = blockIdx.x * 256 + threadIdx.x;
    const int NS = Ldim * 128;
    const int NE = Ldim * 64;

    if (idx < NS + NE) {                // ---- activations (A-side pattern) ----
        const float* src;
        __nv_bfloat16* dst;
        int kg;
        if (idx < NS) {
            int row = idx >> 7; kg = idx & 127;
            src = states + (size_t)row * Sdim;
            dst = g_Ss + (size_t)row * 3072;
        } else {
            int r2 = idx - NS;
            int row = r2 >> 6; kg = r2 & 63;
            src = embeds + (size_t)row * Edim;
            dst = g_Es + (size_t)row * 1536;
        }
        float4 v0 = *(const float4*)(src + kg * 8);
        float4 v1 = *(const float4*)(src + kg * 8 + 4);
        float e[8] = {v0.x, v0.y, v0.z, v0.w, v1.x, v1.y, v1.z, v1.w};
        __align__(16) __nv_bfloat16 t[24];
#pragma unroll
        for (int q = 0; q < 8; q++) {
            __nv_bfloat16 h = __float2bfloat16(e[q]);
            __nv_bfloat16 l = __float2bfloat16(e[q] - __bfloat162float(h));
            t[3 * q] = h; t[3 * q + 1] = l; t[3 * q + 2] = h;
        }
        uint4* d4 = (uint4*)(dst + kg * 24);
        const uint4* s4 = (const uint4*)t;
        d4[0] = s4[0]; d4[1] = s4[1]; d4[2] = s4[2];
        return;
    }
    idx -= NS + NE;                     // ---- weights (B-side pattern) ----

    float e[8];
    __nv_bfloat16* dst;
    if (idx < 61440) {                  // g_W1s: 3 tiles, K=1024
        int t = idx / 20480, r = idx % 20480;
        int kg = r / 160, n = r % 160;
#pragma unroll
        for (int q = 0; q < 8; q++) {
            int k = kg * 8 + q;
            float v = 0.f;
            if (n < Hdim)
                v = (t == 0) ? sW1[(size_t)k * Hdim + n]
                  : (t == 1) ? sW1[(size_t)(1024 + k) * Hdim + n]
                             : aW1[(size_t)k * Hdim + n];
            e[q] = v;
        }
        dst = g_W1s + ((size_t)t * 160 + n) * 3072 + kg * 24;
    } else if (idx < 71680) {           // g_WCs: K=512
        int r = idx - 61440;
        int kg = r / 160, n = r % 160;
#pragma unroll
        for (int q = 0; q < 8; q++) {
            int k = kg * 8 + q;
            e[q] = (n < Hdim) ? sW1[(size_t)(2048 + k) * Hdim + n] : 0.f;
        }
        dst = g_WCs + (size_t)n * 1536 + kg * 24;
    } else if (idx < 74880) {           // g_Wl2s
        int r = idx - 71680;
        int kg = r / 160, n = r % 160;
#pragma unroll
        for (int q = 0; q < 8; q++) {
            int k = kg * 8 + q;
            e[q] = (n < Hdim && k < Hdim) ? aW2[(size_t)k * Hdim + n] : 0.f;
        }
        dst = g_Wl2s + (size_t)n * 480 + kg * 24;
    } else if (idx < 78080) {           // g_W2s
        int r = idx - 74880;
        int kg = r / 160, n = r % 160;
#pragma unroll
        for (int q = 0; q < 8; q++) {
            int k = kg * 8 + q;
            e[q] = (n < Hdim && k < Hdim) ? sW2[(size_t)k * Hdim + n] : 0.f;
        }
        dst = g_W2s + (size_t)n * 480 + kg * 24;
    } else if (idx < 78240) {
        int c = idx - 78080;
        g_sW3p[c] = (c < Hdim) ? sW3[c] : 0.f;
        g_sb2p[c] = (c < Hdim) ? sb2[c] : 0.f;
        return;
    } else if (idx < 78400) {
        int c = idx - 78240;
        g_aW3p[c] = (c < Hdim) ? aW3[c] : 0.f;
        g_ab2p[c] = (c < Hdim) ? ab2[c] : 0.f;
        return;
    } else return;

    __align__(16) __nv_bfloat16 t24[24];
#pragma unroll
    for (int q = 0; q < 8; q++) {
        __nv_bfloat16 h = __float2bfloat16(e[q]);
        __nv_bfloat16 l = __float2bfloat16(e[q] - __bfloat162float(h));
        t24[3 * q] = h; t24[3 * q + 1] = h; t24[3 * q + 2] = l;
    }
    uint4* d4 = (uint4*)dst;
    const uint4* s4 = (const uint4*)t24;
    d4[0] = s4[0]; d4[1] = s4[1]; d4[2] = s4[2];
}

// ---------------------------------------------------------------------------
// Tensor-core GEMM. Templated BM = 32*MI. 320 threads = 10 warps (2m x 5n).
// job 3 reads A as fp32 (g_X) and converts to triplets during smem staging.
// ---------------------------------------------------------------------------
template<int MI, int MINB>
__global__ __launch_bounds__(320, MINB)
void mma_main(int job, const float* __restrict__ bias,
              const float* __restrict__ sc, float* __restrict__ outv)
{
    constexpr int BMt = 32 * MI;
    constexpr int NA  = (BMt * 6 + 319) / 320;
    extern __shared__ char smx[];
    __nv_bfloat16* Ab[2] = {(__nv_bfloat16*)smx,
                            (__nv_bfloat16*)smx + BMt * 56};
    __nv_bfloat16* Bb[2] = {(__nv_bfloat16*)smx + 2 * BMt * 56,
                            (__nv_bfloat16*)smx + 2 * BMt * 56 + 8960};
    float* red = (float*)(smx + (2 * BMt * 56 + 17920) * 2);

    const __nv_bfloat16 *Asrc = nullptr, *Wsrc;
    int Kp, nch, mode, Tmax = 0;
    bool a32 = false;
    float* dst = nullptr;
    const float *wvec = nullptr, *bvec = nullptr;
    if (job == 0) {
        int y = blockIdx.y;
        if (y < 3) {
            Asrc = g_Ss; Kp = 3072; nch = 64;
            Wsrc = g_W1s + (size_t)y * 160 * 3072;
            if (y == 0)      { dst = g_A; mode = 0; }
            else if (y == 1) { dst = g_B; mode = 0; }
            else             { mode = 3; }
        } else {
            Asrc = g_Es; Kp = 1536; nch = 32; Wsrc = g_WCs; dst = g_C; mode = 0;
        }
    } else if (job == 2) {
        Asrc = g_H1s; Kp = 480; nch = 10; Wsrc = g_Wl2s; mode = 2;
        wvec = g_aW3p; bvec = g_ab2p; dst = g_attn; Tmax = Ldim;
    } else {
        a32 = true; Kp = 480; nch = 10; Wsrc = g_W2s; mode = 2;
        wvec = g_sW3p; bvec = g_sb2p; dst = outv; Tmax = Ttot;
    }

    const int tid  = threadIdx.x;
    const int lane = tid & 31;
    const int w    = tid >> 5;
    const int wm   = w / 5;
    const int wn   = w % 5;
    const int g    = lane >> 2;
    const int tg   = lane & 3;
    const int row0 = blockIdx.x * BMt;
    const int abase = (wm * 16 * MI + g) * 28 + tg;
    const int bbase = (wn * 32 + g) * 28 + tg;

    float acc[MI][4][4];
#pragma unroll
    for (int i = 0; i < MI; i++)
#pragma unroll
        for (int j = 0; j < 4; j++)
#pragma unroll
            for (int k = 0; k < 4; k++) acc[i][j][k] = 0.f;

    uint4 rA[NA], rB[3];
    float4 fA;

    auto loadAB = [&](int ch) {
        if (a32) {
            if (tid < BMt * 4) {
                int m = tid >> 2, q = tid & 3;
                fA = *(const float4*)(g_X + (size_t)(row0 + m) * HP + ch * 16 + q * 4);
            }
        } else {
#pragma unroll
            for (int it = 0; it < NA; it++) {
                int idx = tid + it * 320;
                if (idx < BMt * 6) {
                    int m = idx / 6, q = idx - 6 * m;
                    rA[it] = *(const uint4*)(Asrc + (size_t)(row0 + m) * Kp + ch * 48 + q * 8);
                }
            }
        }
#pragma unroll
        for (int it = 0; it < 3; it++) {
            int idx = tid + it * 320;
            int n = idx / 6, q = idx - 6 * n;
            rB[it] = *(const uint4*)(Wsrc + (size_t)n * Kp + ch * 48 + q * 8);
        }
    };
    auto storeAB = [&](int pp) {
        if (a32) {
            if (tid < BMt * 4) {
                int m = tid >> 2, q = tid & 3;
                float e[4] = {fA.x, fA.y, fA.z, fA.w};
                __align__(8) __nv_bfloat16 t[12];
#pragma unroll
                for (int i2 = 0; i2 < 4; i2++) {
                    __nv_bfloat16 h = __float2bfloat16(e[i2]);
                    __nv_bfloat16 l = __float2bfloat16(e[i2] - __bfloat162float(h));
                    t[3 * i2] = h; t[3 * i2 + 1] = l; t[3 * i2 + 2] = h;
                }
                uint2* d = (uint2*)(Ab[pp] + m * 56 + q * 12);
                const uint2* s = (const uint2*)t;
                d[0] = s[0]; d[1] = s[1]; d[2] = s[2];
            }
        } else {
#pragma unroll
            for (int it = 0; it < NA; it++) {
                int idx = tid + it * 320;
                if (idx < BMt * 6) {
                    int m = idx / 6, q = idx - 6 * m;
                    *(uint4*)(Ab[pp] + m * 56 + q * 8) = rA[it];
                }
            }
        }
#pragma unroll
        for (int it = 0; it < 3; it++) {
            int idx = tid + it * 320;
            int n = idx / 6, q = idx - 6 * n;
            *(uint4*)(Bb[pp] + n * 56 + q * 8) = rB[it];
        }
    };
    auto domma = [&](int pp) {
        const unsigned* As32 = (const unsigned*)Ab[pp];
        const unsigned* Bs32 = (const unsigned*)Bb[pp];
#pragma unroll
        for (int st = 0; st < 3; st++) {
            const int ko = st * 8;
            unsigned b0[4], b1[4];
#pragma unroll
            for (int j = 0; j < 4; j++) {
                b0[j] = Bs32[bbase + j * 224 + ko];
                b1[j] = Bs32[bbase + j * 224 + ko + 4];
            }
#pragma unroll
            for (int i = 0; i < MI; i++) {
                unsigned a0 = As32[abase + i * 448 + ko];
                unsigned a1 = As32[abase + i * 448 + 224 + ko];
                unsigned a2 = As32[abase + i * 448 + ko + 4];
                unsigned a3 = As32[abase + i * 448 + 224 + ko + 4];
#pragma unroll
                for (int j = 0; j < 4; j++) {
                    asm volatile(
                        "mma.sync.aligned.m16n8k16.row.col.f32.bf16.bf16.f32 "
                        "{%0,%1,%2,%3},{%4,%5,%6,%7},{%8,%9},{%0,%1,%2,%3};"
                        : "+f"(acc[i][j][0]), "+f"(acc[i][j][1]),
                          "+f"(acc[i][j][2]), "+f"(acc[i][j][3])
                        : "r"(a0), "r"(a1), "r"(a2), "r"(a3),
                          "r"(b0[j]), "r"(b1[j]));
                }
            }
        }
    };

    loadAB(0);
    storeAB(0);
    __syncthreads();
    int p = 0;
    for (int ch = 0; ch < nch; ch++) {
        bool more = (ch + 1 < nch);
        if (more) loadAB(ch + 1);
        domma(p);
        __syncthreads();
        if (more) { storeAB(p ^ 1); __syncthreads(); }
        p ^= 1;
    }

    if (mode == 0) {
#pragma unroll
        for (int i = 0; i < MI; i++) {
            int r = row0 + wm * 16 * MI + i * 16 + g;
#pragma unroll
            for (int j = 0; j < 4; j++) {
                int c = wn * 32 + j * 8 + 2 * tg;
                if (c < Hdim) {
                    dst[(size_t)r * HP + c]           = acc[i][j][0];
                    dst[(size_t)r * HP + c + 1]       = acc[i][j][1];
                    dst[(size_t)(r + 8) * HP + c]     = acc[i][j][2];
                    dst[(size_t)(r + 8) * HP + c + 1] = acc[i][j][3];
                }
            }
        }
    } else if (mode == 3) {
#pragma unroll
        for (int i = 0; i < MI; i++) {
            int r = row0 + wm * 16 * MI + i * 16 + g;
#pragma unroll
            for (int j = 0; j < 4; j++) {
                int c = wn * 32 + j * 8 + 2 * tg;
                if (c < Hdim) {
                    float b0 = bias[c], b1 = bias[c + 1];
                    float v0 = fmaxf(acc[i][j][0] + b0, 0.f);
                    float v1 = fmaxf(acc[i][j][1] + b1, 0.f);
                    float v2 = fmaxf(acc[i][j][2] + b0, 0.f);
                    float v3 = fmaxf(acc[i][j][3] + b1, 0.f);
#pragma unroll
                    for (int hh = 0; hh < 2; hh++) {
                        float va = hh ? v2 : v0, vb = hh ? v3 : v1;
                        int rr = r + 8 * hh;
                        __nv_bfloat16 ha = __float2bfloat16(va);
                        __nv_bfloat16 la = __float2bfloat16(va - __bfloat162float(ha));
                        __nv_bfloat16 hb = __float2bfloat16(vb);
                        __nv_bfloat16 lb = __float2bfloat16(vb - __bfloat162float(hb));
                        __nv_bfloat162* pt =
                            (__nv_bfloat162*)(g_H1s + (size_t)rr * 480 + 3 * c);
                        pt[0] = __nv_bfloat162{ha, la};
                        pt[1] = __nv_bfloat162{ha, hb};
                        pt[2] = __nv_bfloat162{lb, hb};
                    }
                }
            }
        }
    } else {
#pragma unroll
        for (int i = 0; i < MI; i++) {
            float pl = 0.f, ph = 0.f;
#pragma unroll
            for (int j = 0; j < 4; j++) {
                int c = wn * 32 + j * 8 + 2 * tg;
                float w0 = wvec[c], w1 = wvec[c + 1];
                float s0 = bvec[c], s1 = bvec[c + 1];
                pl += w0 * fmaxf(acc[i][j][0] + s0, 0.f)
                    + w1 * fmaxf(acc[i][j][1] + s1, 0.f);
                ph += w0 * fmaxf(acc[i][j][2] + s0, 0.f)
                    + w1 * fmaxf(acc[i][j][3] + s1, 0.f);
            }
            pl += __shfl_xor_sync(0xffffffffu, pl, 1);
            pl += __shfl_xor_sync(0xffffffffu, pl, 2);
            ph += __shfl_xor_sync(0xffffffffu, ph, 1);
            ph += __shfl_xor_sync(0xffffffffu, ph, 2);
            if (tg == 0) {
                int rl = wm * 16 * MI + i * 16 + g;
                red[rl * 5 + wn]       = pl;
                red[(rl + 8) * 5 + wn] = ph;
            }
        }
        __syncthreads();
        if (tid < BMt) {
            float s = sc[0];
#pragma unroll
            for (int q = 0; q < 5; q++) s += red[tid * 5 + q];
            int t = row0 + tid;
            if (t < Tmax) dst[t] = s;
        }
    }
}

// ---------------------------------------------------------------------------
// Pool v4: block = 8 starts x ALL 10 n; 256 threads (8 warps, 10 rows each).
// grid 512 -> ~3.5 blocks/SM. fp32 output, direct coalesced stores.
// ---------------------------------------------------------------------------
__global__ __launch_bounds__(256)
void pool_kernel(const float* __restrict__ sb1)
{
    __shared__ float As[8][152];
    __shared__ float Bs[17][152];
    __shared__ float Cs[17][152];
    __shared__ float attw[24];
    __shared__ float sb1s[160];

    const int tid = threadIdx.x;
    const int s0  = blockIdx.x * 8;

    if (tid < 160) sb1s[tid] = (tid < Hdim) ? sb1[tid] : 0.f;
    if (tid >= 160 && tid < 177) {
        int i = tid - 160;
        int gg = s0 + i;
        attw[i] = (gg < Ldim) ? g_attn[gg] : 0.f;
    }
    for (int i = tid; i < 8 * 38; i += 256) {
        int r = i / 38, q = i % 38;
        *(float4*)&As[r][q * 4] = *(const float4*)(g_A + (size_t)(s0 + r) * HP + q * 4);
    }
    for (int i = tid; i < 17 * 38; i += 256) {
        int r = i / 38, q = i % 38;
        int gr = s0 + r;
        float4 v = make_float4(0.f, 0.f, 0.f, 0.f);
        if (gr < Ldim) v = *(const float4*)(g_B + (size_t)gr * HP + q * 4);
        *(float4*)&Bs[r][q * 4] = v;
    }
    for (int i = tid; i < 17 * 38; i += 256) {
        int r = i / 38, q = i % 38;
        int gr = s0 + r;
        float4 v = make_float4(0.f, 0.f, 0.f, 0.f);
        if (gr < Ldim) v = *(const float4*)(g_C + (size_t)gr * HP + q * 4);
        *(float4*)&Cs[r][q * 4] = v;
    }
    __syncthreads();

    const int warp = tid >> 5, lane = tid & 31;
#pragma unroll
    for (int rowi = warp; rowi < 80; rowi += 8) {
        const int n     = (rowi >> 3) + 1;
        const int si    = rowi & 7;
        const int start = s0 + si;
        if (start >= Ldim - n + 1) continue;    // warp-uniform

        float wj[MAXN];
        float mx = -1e30f;
        for (int j = 0; j < n; j++) mx = fmaxf(mx, attw[si + j]);
        float ssum = 0.f;
        for (int j = 0; j < n; j++) {
            float e = __expf(attw[si + j] - mx);
            wj[j] = e; ssum += e;
        }
        float inv = 1.f / ssum;

        const int off = (n - 1) * (Ldim + 1) - (n * (n - 1)) / 2;
        float* outp = g_X + (size_t)(off + start) * HP;
#pragma unroll
        for (int k = 0; k < 5; k++) {
            int c = lane + 32 * k;
            if (c < Hdim) {
                float pool = 0.f;
                for (int j = 0; j < n; j++) pool += wj[j] * Cs[si + j][c];
                float v = As[si][c] + Bs[si + n - 1][c] + sb1s[c] + pool * inv;
                outp[c] = fmaxf(v, 0.f);
            }
        }
    }
}

// ---------------------------------------------------------------------------
extern "C" void kernel_launch(void* const* d_in, const int* in_sizes, int n_in,
                              void* d_out, int out_size)
{
    const float* embeds = (const float*)d_in[0];
    const float* states = (const float*)d_in[1];
    const float* aW1    = (const float*)d_in[2];
    const float* ab1    = (const float*)d_in[3];
    const float* aW2    = (const float*)d_in[4];
    const float* ab2    = (const float*)d_in[5];
    const float* aW3    = (const float*)d_in[6];
    const float* ab3    = (const float*)d_in[7];
    const float* sW1    = (const float*)d_in[8];
    const float* sb1    = (const float*)d_in[9];
    const float* sW2    = (const float*)d_in[10];
    const float* sb2    = (const float*)d_in[11];
    const float* sW3    = (const float*)d_in[12];
    const float* sb3    = (const float*)d_in[13];
    float* out = (float*)d_out;

    cudaFuncSetAttribute(mma_main<1, 3>,
                         cudaFuncAttributeMaxDynamicSharedMemorySize, 43648);
    cudaFuncSetAttribute(mma_main<2, 2>,
                         cudaFuncAttributeMaxDynamicSharedMemorySize, 51456);

    // all splits (acts + weights + padded vectors), one launch
    split_all<<<3379, 256>>>(states, embeds, sW1, aW1, aW2, sW2,
                             sW3, sb2, aW3, ab2);
    // precompute GEMMs: g_A, g_B, H1-triplets, g_C  (BM=64, 2 blocks/SM)
    mma_main<2, 2><<<dim3(64, 4), 320, 51456>>>(0, ab1, nullptr, nullptr);
    // attn layer2 + layer3 fused -> g_attn  (BM=32, grid 128)
    mma_main<1, 3><<<dim3(128, 1), 320, 43648>>>(2, nullptr, ab3, nullptr);
    // pooled rows (fp32) -> g_X  (8 starts x all n per block, grid 512)
    pool_kernel<<<512, 256>>>(sb1);
    // big GEMM (fp32 A staged->triplets) + fused layer3 -> out
    mma_main<2, 2><<<dim3(640, 1), 320, 51456>>>(3, nullptr, sb3, out);
}

// round 11
// speedup vs baseline: 1.1362x; 1.1362x over previous
#include <cuda_runtime.h>
#include <cuda_bf16.h>
#include <math.h>

#define Ldim 4096
#define Edim 512
#define Sdim 1024
#define Hdim 150
#define HP   160
#define MAXN 10
#define Ttot 40915
#define TP   40960

// ---------------------------------------------------------------------------
// Device scratch (zero-init; pad regions never written -> stay zero)
// ---------------------------------------------------------------------------
__device__ float g_A[Ldim * HP];
__device__ float g_B[Ldim * HP];
__device__ float g_C[Ldim * HP];
__device__ float g_attn[Ldim];
__device__ float g_X[(size_t)TP * HP];   // pooled rows, fp32 (pad cols stay 0)
__device__ float g_sW3p[HP];
__device__ float g_sb2p[HP];
__device__ float g_aW3p[HP];
__device__ float g_ab2p[HP];

// bf16 hi/lo triplet buffers.  A-side slot pattern: [xh, xl, xh]
//                              B-side slot pattern: [bh, bh, bl]
__device__ __align__(16) __nv_bfloat16 g_H1s[(size_t)Ldim * 480];
__device__ __align__(16) __nv_bfloat16 g_W1s[3 * 160 * 3072];
__device__ __align__(16) __nv_bfloat16 g_WCs[160 * 1536];
__device__ __align__(16) __nv_bfloat16 g_Wl2s[160 * 480];
__device__ __align__(16) __nv_bfloat16 g_W2s[160 * 480];

// ---------------------------------------------------------------------------
// Weight split kernel (weights only now): fp32 W[k][n] -> B-side triplets
// ---------------------------------------------------------------------------
__global__ void split_w(const float* __restrict__ sW1,
                        const float* __restrict__ aW1,
                        const float* __restrict__ aW2,
                        const float* __restrict__ sW2,
                        const float* __restrict__ sW3,
                        const float* __restrict__ sb2,
                        const float* __restrict__ aW3,
                        const float* __restrict__ ab2)
{
    int idx = blockIdx.x * 256 + threadIdx.x;
    float e[8];
    __nv_bfloat16* dst;

    if (idx < 61440) {                  // g_W1s: 3 tiles, K=1024
        int t = idx / 20480, r = idx % 20480;
        int kg = r / 160, n = r % 160;
#pragma unroll
        for (int q = 0; q < 8; q++) {
            int k = kg * 8 + q;
            float v = 0.f;
            if (n < Hdim)
                v = (t == 0) ? sW1[(size_t)k * Hdim + n]
                  : (t == 1) ? sW1[(size_t)(1024 + k) * Hdim + n]
                             : aW1[(size_t)k * Hdim + n];
            e[q] = v;
        }
        dst = g_W1s + ((size_t)t * 160 + n) * 3072 + kg * 24;
    } else if (idx < 71680) {           // g_WCs: K=512
        int r = idx - 61440;
        int kg = r / 160, n = r % 160;
#pragma unroll
        for (int q = 0; q < 8; q++) {
            int k = kg * 8 + q;
            e[q] = (n < Hdim) ? sW1[(size_t)(2048 + k) * Hdim + n] : 0.f;
        }
        dst = g_WCs + (size_t)n * 1536 + kg * 24;
    } else if (idx < 74880) {           // g_Wl2s
        int r = idx - 71680;
        int kg = r / 160, n = r % 160;
#pragma unroll
        for (int q = 0; q < 8; q++) {
            int k = kg * 8 + q;
            e[q] = (n < Hdim && k < Hdim) ? aW2[(size_t)k * Hdim + n] : 0.f;
        }
        dst = g_Wl2s + (size_t)n * 480 + kg * 24;
    } else if (idx < 78080) {           // g_W2s
        int r = idx - 74880;
        int kg = r / 160, n = r % 160;
#pragma unroll
        for (int q = 0; q < 8; q++) {
            int k = kg * 8 + q;
            e[q] = (n < Hdim && k < Hdim) ? sW2[(size_t)k * Hdim + n] : 0.f;
        }
        dst = g_W2s + (size_t)n * 480 + kg * 24;
    } else if (idx < 78240) {
        int c = idx - 78080;
        g_sW3p[c] = (c < Hdim) ? sW3[c] : 0.f;
        g_sb2p[c] = (c < Hdim) ? sb2[c] : 0.f;
        return;
    } else if (idx < 78400) {
        int c = idx - 78240;
        g_aW3p[c] = (c < Hdim) ? aW3[c] : 0.f;
        g_ab2p[c] = (c < Hdim) ? ab2[c] : 0.f;
        return;
    } else return;

    __align__(16) __nv_bfloat16 t24[24];
#pragma unroll
    for (int q = 0; q < 8; q++) {
        __nv_bfloat16 h = __float2bfloat16(e[q]);
        __nv_bfloat16 l = __float2bfloat16(e[q] - __bfloat162float(h));
        t24[3 * q] = h; t24[3 * q + 1] = h; t24[3 * q + 2] = l;
    }
    uint4* d4 = (uint4*)dst;
    const uint4* s4 = (const uint4*)t24;
    d4[0] = s4[0]; d4[1] = s4[1]; d4[2] = s4[2];
}

// ---------------------------------------------------------------------------
// Tensor-core GEMM. Templated BM = 32*MI. 320 threads = 10 warps (2m x 5n).
// A-side: either pre-split triplets (job 2) or fp32 converted during staging
// (jobs 0, 3). B-side: pre-split triplet weights.
// ---------------------------------------------------------------------------
template<int MI, int MINB>
__global__ __launch_bounds__(320, MINB)
void mma_main(int job, const float* __restrict__ bias,
              const float* __restrict__ sc, float* __restrict__ outv,
              const float* __restrict__ Xf32)
{
    constexpr int BMt  = 32 * MI;
    constexpr int NA   = (BMt * 6 + 319) / 320;   // triplet-A uint4 per thread
    constexpr int NA32 = (BMt * 4 + 319) / 320;   // fp32-A float4 per thread
    extern __shared__ char smx[];
    __nv_bfloat16* Ab[2] = {(__nv_bfloat16*)smx,
                            (__nv_bfloat16*)smx + BMt * 56};
    __nv_bfloat16* Bb[2] = {(__nv_bfloat16*)smx + 2 * BMt * 56,
                            (__nv_bfloat16*)smx + 2 * BMt * 56 + 8960};
    float* red = (float*)(smx + (2 * BMt * 56 + 17920) * 2);

    const __nv_bfloat16 *Asrc = nullptr, *Wsrc;
    const float* Asrc32 = nullptr;
    int lda32 = 0;
    int nch, mode, Tmax = 0;
    int Kp;                             // triplet row length (A trip / B)
    float* dst = nullptr;
    const float *wvec = nullptr, *bvec = nullptr;
    if (job == 0) {
        int y = blockIdx.y;
        if (y < 3) {
            Asrc32 = Xf32; lda32 = Sdim; Kp = 3072; nch = 64;
            Wsrc = g_W1s + (size_t)y * 160 * 3072;
            if (y == 0)      { dst = g_A; mode = 0; }
            else if (y == 1) { dst = g_B; mode = 0; }
            else             { mode = 3; }
        } else {
            Asrc32 = outv;  // embeds passed via outv slot for job0
            lda32 = Edim; Kp = 1536; nch = 32; Wsrc = g_WCs; dst = g_C; mode = 0;
        }
    } else if (job == 2) {
        Asrc = g_H1s; Kp = 480; nch = 10; Wsrc = g_Wl2s; mode = 2;
        wvec = g_aW3p; bvec = g_ab2p; dst = g_attn; Tmax = Ldim;
    } else {
        Asrc32 = g_X; lda32 = HP; Kp = 480; nch = 10; Wsrc = g_W2s; mode = 2;
        wvec = g_sW3p; bvec = g_sb2p; dst = outv; Tmax = Ttot;
    }
    const bool a32 = (Asrc32 != nullptr);

    const int tid  = threadIdx.x;
    const int lane = tid & 31;
    const int w    = tid >> 5;
    const int wm   = w / 5;
    const int wn   = w % 5;
    const int g    = lane >> 2;
    const int tg   = lane & 3;
    const int row0 = blockIdx.x * BMt;
    const int abase = (wm * 16 * MI + g) * 28 + tg;
    const int bbase = (wn * 32 + g) * 28 + tg;

    float acc[MI][4][4];
#pragma unroll
    for (int i = 0; i < MI; i++)
#pragma unroll
        for (int j = 0; j < 4; j++)
#pragma unroll
            for (int k = 0; k < 4; k++) acc[i][j][k] = 0.f;

    uint4 rA[NA], rB[3];
    float4 fA[NA32];

    auto loadAB = [&](int ch) {
        if (a32) {
#pragma unroll
            for (int it = 0; it < NA32; it++) {
                int idx = tid + it * 320;
                if (idx < BMt * 4) {
                    int m = idx >> 2, q = idx & 3;
                    fA[it] = *(const float4*)(Asrc32 + (size_t)(row0 + m) * lda32
                                              + ch * 16 + q * 4);
                }
            }
        } else {
#pragma unroll
            for (int it = 0; it < NA; it++) {
                int idx = tid + it * 320;
                if (idx < BMt * 6) {
                    int m = idx / 6, q = idx - 6 * m;
                    rA[it] = *(const uint4*)(Asrc + (size_t)(row0 + m) * Kp + ch * 48 + q * 8);
                }
            }
        }
#pragma unroll
        for (int it = 0; it < 3; it++) {
            int idx = tid + it * 320;
            int n = idx / 6, q = idx - 6 * n;
            rB[it] = *(const uint4*)(Wsrc + (size_t)n * Kp + ch * 48 + q * 8);
        }
    };
    auto storeAB = [&](int pp) {
        if (a32) {
#pragma unroll
            for (int it = 0; it < NA32; it++) {
                int idx = tid + it * 320;
                if (idx < BMt * 4) {
                    int m = idx >> 2, q = idx & 3;
                    float e[4] = {fA[it].x, fA[it].y, fA[it].z, fA[it].w};
                    __align__(8) __nv_bfloat16 t[12];
#pragma unroll
                    for (int i2 = 0; i2 < 4; i2++) {
                        __nv_bfloat16 h = __float2bfloat16(e[i2]);
                        __nv_bfloat16 l = __float2bfloat16(e[i2] - __bfloat162float(h));
                        t[3 * i2] = h; t[3 * i2 + 1] = l; t[3 * i2 + 2] = h;
                    }
                    uint2* d = (uint2*)(Ab[pp] + m * 56 + q * 12);
                    const uint2* s = (const uint2*)t;
                    d[0] = s[0]; d[1] = s[1]; d[2] = s[2];
                }
            }
        } else {
#pragma unroll
            for (int it = 0; it < NA; it++) {
                int idx = tid + it * 320;
                if (idx < BMt * 6) {
                    int m = idx / 6, q = idx - 6 * m;
                    *(uint4*)(Ab[pp] + m * 56 + q * 8) = rA[it];
                }
            }
        }
#pragma unroll
        for (int it = 0; it < 3; it++) {
            int idx = tid + it * 320;
            int n = idx / 6, q = idx - 6 * n;
            *(uint4*)(Bb[pp] + n * 56 + q * 8) = rB[it];
        }
    };
    auto domma = [&](int pp) {
        const unsigned* As32 = (const unsigned*)Ab[pp];
        const unsigned* Bs32 = (const unsigned*)Bb[pp];
#pragma unroll
        for (int st = 0; st < 3; st++) {
            const int ko = st * 8;
            unsigned b0[4], b1[4];
#pragma unroll
            for (int j = 0; j < 4; j++) {
                b0[j] = Bs32[bbase + j * 224 + ko];
                b1[j] = Bs32[bbase + j * 224 + ko + 4];
            }
#pragma unroll
            for (int i = 0; i < MI; i++) {
                unsigned a0 = As32[abase + i * 448 + ko];
                unsigned a1 = As32[abase + i * 448 + 224 + ko];
                unsigned a2 = As32[abase + i * 448 + ko + 4];
                unsigned a3 = As32[abase + i * 448 + 224 + ko + 4];
#pragma unroll
                for (int j = 0; j < 4; j++) {
                    asm volatile(
                        "mma.sync.aligned.m16n8k16.row.col.f32.bf16.bf16.f32 "
                        "{%0,%1,%2,%3},{%4,%5,%6,%7},{%8,%9},{%0,%1,%2,%3};"
                        : "+f"(acc[i][j][0]), "+f"(acc[i][j][1]),
                          "+f"(acc[i][j][2]), "+f"(acc[i][j][3])
                        : "r"(a0), "r"(a1), "r"(a2), "r"(a3),
                          "r"(b0[j]), "r"(b1[j]));
                }
            }
        }
    };

    loadAB(0);
    storeAB(0);
    __syncthreads();
    int p = 0;
    for (int ch = 0; ch < nch; ch++) {
        bool more = (ch + 1 < nch);
        if (more) loadAB(ch + 1);
        domma(p);
        __syncthreads();
        if (more) { storeAB(p ^ 1); __syncthreads(); }
        p ^= 1;
    }

    if (mode == 0) {
#pragma unroll
        for (int i = 0; i < MI; i++) {
            int r = row0 + wm * 16 * MI + i * 16 + g;
#pragma unroll
            for (int j = 0; j < 4; j++) {
                int c = wn * 32 + j * 8 + 2 * tg;
                if (c < Hdim) {
                    dst[(size_t)r * HP + c]           = acc[i][j][0];
                    dst[(size_t)r * HP + c + 1]       = acc[i][j][1];
                    dst[(size_t)(r + 8) * HP + c]     = acc[i][j][2];
                    dst[(size_t)(r + 8) * HP + c + 1] = acc[i][j][3];
                }
            }
        }
    } else if (mode == 3) {
#pragma unroll
        for (int i = 0; i < MI; i++) {
            int r = row0 + wm * 16 * MI + i * 16 + g;
#pragma unroll
            for (int j = 0; j < 4; j++) {
                int c = wn * 32 + j * 8 + 2 * tg;
                if (c < Hdim) {
                    float b0 = bias[c], b1 = bias[c + 1];
                    float v0 = fmaxf(acc[i][j][0] + b0, 0.f);
                    float v1 = fmaxf(acc[i][j][1] + b1, 0.f);
                    float v2 = fmaxf(acc[i][j][2] + b0, 0.f);
                    float v3 = fmaxf(acc[i][j][3] + b1, 0.f);
#pragma unroll
                    for (int hh = 0; hh < 2; hh++) {
                        float va = hh ? v2 : v0, vb = hh ? v3 : v1;
                        int rr = r + 8 * hh;
                        __nv_bfloat16 ha = __float2bfloat16(va);
                        __nv_bfloat16 la = __float2bfloat16(va - __bfloat162float(ha));
                        __nv_bfloat16 hb = __float2bfloat16(vb);
                        __nv_bfloat16 lb = __float2bfloat16(vb - __bfloat162float(hb));
                        __nv_bfloat162* pt =
                            (__nv_bfloat162*)(g_H1s + (size_t)rr * 480 + 3 * c);
                        pt[0] = __nv_bfloat162{ha, la};
                        pt[1] = __nv_bfloat162{ha, hb};
                        pt[2] = __nv_bfloat162{lb, hb};
                    }
                }
            }
        }
    } else {
#pragma unroll
        for (int i = 0; i < MI; i++) {
            float pl = 0.f, ph = 0.f;
#pragma unroll
            for (int j = 0; j < 4; j++) {
                int c = wn * 32 + j * 8 + 2 * tg;
                float w0 = wvec[c], w1 = wvec[c + 1];
                float s0 = bvec[c], s1 = bvec[c + 1];
                pl += w0 * fmaxf(acc[i][j][0] + s0, 0.f)
                    + w1 * fmaxf(acc[i][j][1] + s1, 0.f);
                ph += w0 * fmaxf(acc[i][j][2] + s0, 0.f)
                    + w1 * fmaxf(acc[i][j][3] + s1, 0.f);
            }
            pl += __shfl_xor_sync(0xffffffffu, pl, 1);
            pl += __shfl_xor_sync(0xffffffffu, pl, 2);
            ph += __shfl_xor_sync(0xffffffffu, ph, 1);
            ph += __shfl_xor_sync(0xffffffffu, ph, 2);
            if (tg == 0) {
                int rl = wm * 16 * MI + i * 16 + g;
                red[rl * 5 + wn]       = pl;
                red[(rl + 8) * 5 + wn] = ph;
            }
        }
        __syncthreads();
        if (tid < BMt) {
            float s = sc[0];
#pragma unroll
            for (int q = 0; q < 5; q++) s += red[tid * 5 + q];
            int t = row0 + tid;
            if (t < Tmax) dst[t] = s;
        }
    }
}

// ---------------------------------------------------------------------------
// Pool v4: block = 8 starts x ALL 10 n; 256 threads (8 warps, 10 rows each).
// ---------------------------------------------------------------------------
__global__ __launch_bounds__(256)
void pool_kernel(const float* __restrict__ sb1)
{
    __shared__ float As[8][152];
    __shared__ float Bs[17][152];
    __shared__ float Cs[17][152];
    __shared__ float attw[24];
    __shared__ float sb1s[160];

    const int tid = threadIdx.x;
    const int s0  = blockIdx.x * 8;

    if (tid < 160) sb1s[tid] = (tid < Hdim) ? sb1[tid] : 0.f;
    if (tid >= 160 && tid < 177) {
        int i = tid - 160;
        int gg = s0 + i;
        attw[i] = (gg < Ldim) ? g_attn[gg] : 0.f;
    }
    for (int i = tid; i < 8 * 38; i += 256) {
        int r = i / 38, q = i % 38;
        *(float4*)&As[r][q * 4] = *(const float4*)(g_A + (size_t)(s0 + r) * HP + q * 4);
    }
    for (int i = tid; i < 17 * 38; i += 256) {
        int r = i / 38, q = i % 38;
        int gr = s0 + r;
        float4 v = make_float4(0.f, 0.f, 0.f, 0.f);
        if (gr < Ldim) v = *(const float4*)(g_B + (size_t)gr * HP + q * 4);
        *(float4*)&Bs[r][q * 4] = v;
    }
    for (int i = tid; i < 17 * 38; i += 256) {
        int r = i / 38, q = i % 38;
        int gr = s0 + r;
        float4 v = make_float4(0.f, 0.f, 0.f, 0.f);
        if (gr < Ldim) v = *(const float4*)(g_C + (size_t)gr * HP + q * 4);
        *(float4*)&Cs[r][q * 4] = v;
    }
    __syncthreads();

    const int warp = tid >> 5, lane = tid & 31;
#pragma unroll
    for (int rowi = warp; rowi < 80; rowi += 8) {
        const int n     = (rowi >> 3) + 1;
        const int si    = rowi & 7;
        const int start = s0 + si;
        if (start >= Ldim - n + 1) continue;    // warp-uniform

        float wj[MAXN];
        float mx = -1e30f;
        for (int j = 0; j < n; j++) mx = fmaxf(mx, attw[si + j]);
        float ssum = 0.f;
        for (int j = 0; j < n; j++) {
            float e = __expf(attw[si + j] - mx);
            wj[j] = e; ssum += e;
        }
        float inv = 1.f / ssum;

        const int off = (n - 1) * (Ldim + 1) - (n * (n - 1)) / 2;
        float* outp = g_X + (size_t)(off + start) * HP;
#pragma unroll
        for (int k = 0; k < 5; k++) {
            int c = lane + 32 * k;
            if (c < Hdim) {
                float pool = 0.f;
                for (int j = 0; j < n; j++) pool += wj[j] * Cs[si + j][c];
                float v = As[si][c] + Bs[si + n - 1][c] + sb1s[c] + pool * inv;
                outp[c] = fmaxf(v, 0.f);
            }
        }
    }
}

// ---------------------------------------------------------------------------
extern "C" void kernel_launch(void* const* d_in, const int* in_sizes, int n_in,
                              void* d_out, int out_size)
{
    const float* embeds = (const float*)d_in[0];
    const float* states = (const float*)d_in[1];
    const float* aW1    = (const float*)d_in[2];
    const float* ab1    = (const float*)d_in[3];
    const float* aW2    = (const float*)d_in[4];
    const float* ab2    = (const float*)d_in[5];
    const float* aW3    = (const float*)d_in[6];
    const float* ab3    = (const float*)d_in[7];
    const float* sW1    = (const float*)d_in[8];
    const float* sb1    = (const float*)d_in[9];
    const float* sW2    = (const float*)d_in[10];
    const float* sb2    = (const float*)d_in[11];
    const float* sW3    = (const float*)d_in[12];
    const float* sb3    = (const float*)d_in[13];
    float* out = (float*)d_out;

    cudaFuncSetAttribute(mma_main<4, 1>,
                         cudaFuncAttributeMaxDynamicSharedMemorySize, 67072);
    cudaFuncSetAttribute(mma_main<1, 3>,
                         cudaFuncAttributeMaxDynamicSharedMemorySize, 43648);
    cudaFuncSetAttribute(mma_main<2, 2>,
                         cudaFuncAttributeMaxDynamicSharedMemorySize, 51456);

    // weight splits + padded vectors only (activations read fp32 directly)
    split_w<<<307, 256>>>(sW1, aW1, aW2, sW2, sW3, sb2, aW3, ab2);
    // precompute GEMMs: g_A, g_B, H1-triplets, g_C (BM=128; fp32 A staging)
    // note: states via Xf32 arg, embeds via outv arg (repurposed for job 0)
    mma_main<4, 1><<<dim3(32, 4), 320, 67072>>>(0, ab1, nullptr,
                                                const_cast<float*>(embeds), states);
    // attn layer2 + layer3 fused -> g_attn  (BM=32, grid 128)
    mma_main<1, 3><<<dim3(128, 1), 320, 43648>>>(2, nullptr, ab3, nullptr, nullptr);
    // pooled rows (fp32) -> g_X  (8 starts x all n per block, grid 512)
    pool_kernel<<<512, 256>>>(sb1);
    // big GEMM (fp32 A staged->triplets) + fused layer3 -> out
    mma_main<2, 2><<<dim3(640, 1), 320, 51456>>>(3, nullptr, sb3, out, nullptr);
}